// round 16
// baseline (speedup 1.0000x reference)
#include <cuda_runtime.h>
#include <cuda_fp16.h>
#include <cstdint>

#define NNODES 50000
#define NEDGES 850000
#define IN_DIM 256
#define HID 32
#define H1 8
#define OUT_DIM 64
#define HD1 (H1*HID)   // 256
#define KDIM 256

// ---------------- scratch ----------------
__device__ __align__(16) __half g_W1t[HD1 * KDIM];
__device__ __align__(16) __half g_W2t[OUT_DIM * KDIM];
__device__ __align__(16) __half g_feat1h[NNODES * HD1];
__device__ __align__(16) __half g_h1h[NNODES * HD1];
__device__ __align__(16) __half g_feat2h[NNODES * OUT_DIM];
__device__ __align__(16) float  g_el1[NNODES * H1];
__device__ __align__(16) float  g_er1[NNODES * H1];
__device__ __align__(16) float  g_el2[NNODES];
__device__ __align__(16) float  g_er2[NNODES];
__device__ __align__(16) int    g_cnt[NNODES];
__device__ __align__(16) int    g_off[NNODES + 1];
__device__ __align__(16) int    g_cur[NNODES];
__device__ __align__(16) int    g_csr_src[NEDGES];

#define CPA16(dst, src, sz) \
    asm volatile("cp.async.cg.shared.global [%0], [%1], 16, %2;" :: "r"(dst), "l"(src), "r"(sz) : "memory")
#define CP_COMMIT() asm volatile("cp.async.commit_group;" ::: "memory")
#define CP_WAIT1()  asm volatile("cp.async.wait_group 1;" ::: "memory")

#define LDSM_X4(r0, r1, r2, r3, addr) \
    asm volatile("ldmatrix.sync.aligned.m8n8.x4.shared.b16 {%0,%1,%2,%3}, [%4];" \
        : "=r"(r0), "=r"(r1), "=r"(r2), "=r"(r3) : "r"(addr))

__device__ __forceinline__ uint32_t smem_u32(const void* p) {
    uint32_t a;
    asm("{ .reg .u64 t; cvta.to.shared.u64 t, %1; cvt.u32.u64 %0, t; }" : "=r"(a) : "l"(p));
    return a;
}
__device__ __forceinline__ uint32_t h2_bits(__half2 h) {
    uint32_t u;
    memcpy(&u, &h, 4);
    return u;
}

__device__ __forceinline__ void mma_f16(float c[4], const uint32_t a[4], const uint32_t b[2]) {
    asm("mma.sync.aligned.m16n8k16.row.col.f32.f16.f16.f32 "
        "{%0,%1,%2,%3}, {%4,%5,%6,%7}, {%8,%9}, {%0,%1,%2,%3};"
        : "+f"(c[0]), "+f"(c[1]), "+f"(c[2]), "+f"(c[3])
        : "r"(a[0]), "r"(a[1]), "r"(a[2]), "r"(a[3]), "r"(b[0]), "r"(b[1]));
}

// ---------------- prep: weight transposes only ----------------
__global__ void prepw_kernel(const float* __restrict__ W1, const float* __restrict__ W2) {
    int b = blockIdx.x;
    if (b < 256) {
        int i = b * 256 + threadIdx.x;
        int n = i >> 8, k = i & 255;
        g_W1t[i] = __float2half(W1[k * HD1 + n]);
    } else {
        int i = (b - 256) * 256 + threadIdx.x;
        int n = i >> 8, k = i & 255;
        g_W2t[i] = __float2half(W2[k * OUT_DIM + n]);
    }
}

// ---------------- GEMM1: fp16 mma + ldmatrix; A converted fp32->fp16 in-kernel ----------------
__global__ __launch_bounds__(256) void hgemm1_kernel(
    const float* __restrict__ A, int M, const float* __restrict__ al, const float* __restrict__ ar)
{
    __shared__ __align__(16) __half Asm[2][128 * 40];
    __shared__ __align__(16) __half Bsm[2][128 * 40];

    const int tid = threadIdx.x;
    const int lane = tid & 31;
    const int warp = tid >> 5;
    const int g = lane >> 2;
    const int t = lane & 3;
    const int warpRow = (warp & 3) * 32;
    const int warpCol = (warp >> 2) * 64;
    const int blockRow = blockIdx.y * 128;
    const int colbase = blockIdx.x * 128;

    const int arow = tid >> 1;
    const int kh = (tid & 1) * 16;
    const int agr = blockRow + arow;
    const bool aval = agr < M;
    const float* aSrc = A + (size_t)agr * KDIM + kh;
    __half* aDst0 = &Asm[0][arow * 40 + kh];

    const int bcol = tid >> 1;
    const int bseg = (tid & 1) * 16;
    const __half* bSrc = g_W1t + (size_t)(colbase + bcol) * KDIM + bseg;
    const uint32_t bD0 = smem_u32(&Bsm[0][bcol * 40 + bseg]);
    const uint32_t bD1 = smem_u32(&Bsm[1][bcol * 40 + bseg]);

    const uint32_t aL0 = smem_u32(&Asm[0][0]) + (warpRow + (lane & 15)) * 80 + (lane >> 4) * 16;
    const uint32_t bL0 = smem_u32(&Bsm[0][0]) + (warpCol + (lane & 7) + ((lane >> 4) << 3)) * 80 + (((lane >> 3) & 1) * 16);

    float acc[2][8][4];
#pragma unroll
    for (int mi = 0; mi < 2; mi++)
#pragma unroll
        for (int ni = 0; ni < 8; ni++)
#pragma unroll
            for (int k = 0; k < 4; k++) acc[mi][ni][k] = 0.f;

    float4 av[4];
    auto ldgA = [&](int c) {
#pragma unroll
        for (int q = 0; q < 4; q++)
            av[q] = aval ? *(const float4*)(aSrc + c * 32 + q * 4)
                         : make_float4(0.f, 0.f, 0.f, 0.f);
    };
    auto stsA = [&](int buf) {
        __half* d = aDst0 + buf * (128 * 40);
        uint4 w0, w1;
        w0.x = h2_bits(__floats2half2_rn(av[0].x, av[0].y));
        w0.y = h2_bits(__floats2half2_rn(av[0].z, av[0].w));
        w0.z = h2_bits(__floats2half2_rn(av[1].x, av[1].y));
        w0.w = h2_bits(__floats2half2_rn(av[1].z, av[1].w));
        w1.x = h2_bits(__floats2half2_rn(av[2].x, av[2].y));
        w1.y = h2_bits(__floats2half2_rn(av[2].z, av[2].w));
        w1.z = h2_bits(__floats2half2_rn(av[3].x, av[3].y));
        w1.w = h2_bits(__floats2half2_rn(av[3].z, av[3].w));
        *(uint4*)d = w0;
        *(uint4*)(d + 8) = w1;
    };
    auto cpB = [&](int c, int buf) {
        const __half* s = bSrc + c * 32;
        uint32_t d = buf ? bD1 : bD0;
        CPA16(d, s, 16);
        CPA16(d + 16, s + 8, 16);
    };

    ldgA(0); stsA(0);
    cpB(0, 0); CP_COMMIT();
    ldgA(1);

    for (int c = 0; c < 8; c++) {
        const int buf = c & 1;
        if (c < 7) cpB(c + 1, buf ^ 1);
        CP_COMMIT();
        CP_WAIT1();
        __syncthreads();

        const uint32_t aB = aL0 + buf * 10240;
        const uint32_t bB = bL0 + buf * 10240;
#pragma unroll
        for (int s = 0; s < 2; s++) {
            uint32_t afr[2][4], bfr[8][2];
#pragma unroll
            for (int mi = 0; mi < 2; mi++)
                LDSM_X4(afr[mi][0], afr[mi][1], afr[mi][2], afr[mi][3],
                        aB + mi * (16 * 80) + s * 32);
#pragma unroll
            for (int p = 0; p < 4; p++)
                LDSM_X4(bfr[2 * p][0], bfr[2 * p][1], bfr[2 * p + 1][0], bfr[2 * p + 1][1],
                        bB + p * (16 * 80) + s * 32);
#pragma unroll
            for (int mi = 0; mi < 2; mi++)
#pragma unroll
                for (int ni = 0; ni < 8; ni++)
                    mma_f16(acc[mi][ni], afr[mi], bfr[ni]);
        }
        if (c < 7) {
            stsA(buf ^ 1);
            if (c < 6) ldgA(c + 2);
        }
        __syncthreads();
    }

    const int head0 = (colbase + warpCol) >> 5;
#pragma unroll
    for (int mi = 0; mi < 2; mi++) {
        const int r0 = blockRow + warpRow + mi * 16 + g;
        const int r1 = r0 + 8;
        const bool v0 = r0 < M, v1 = r1 < M;
        float elL[2] = {0.f, 0.f}, erL[2] = {0.f, 0.f};
        float elH[2] = {0.f, 0.f}, erH[2] = {0.f, 0.f};
#pragma unroll
        for (int ni = 0; ni < 8; ni++) {
            const int hsel = ni >> 2;
            const int col = colbase + warpCol + ni * 8 + 2 * t;
            float c0 = acc[mi][ni][0], c1 = acc[mi][ni][1];
            float c2 = acc[mi][ni][2], c3 = acc[mi][ni][3];
            float a0 = al[col], a1 = al[col + 1];
            float q0 = ar[col], q1 = ar[col + 1];
            elL[hsel] += c0 * a0 + c1 * a1;  erL[hsel] += c0 * q0 + c1 * q1;
            elH[hsel] += c2 * a0 + c3 * a1;  erH[hsel] += c2 * q0 + c3 * q1;
            if (v0) *(uint32_t*)&g_feat1h[(size_t)r0 * HD1 + col] = h2_bits(__floats2half2_rn(c0, c1));
            if (v1) *(uint32_t*)&g_feat1h[(size_t)r1 * HD1 + col] = h2_bits(__floats2half2_rn(c2, c3));
        }
#pragma unroll
        for (int hsel = 0; hsel < 2; hsel++) {
#pragma unroll
            for (int o = 1; o <= 2; o <<= 1) {
                elL[hsel] += __shfl_xor_sync(0xffffffffu, elL[hsel], o);
                erL[hsel] += __shfl_xor_sync(0xffffffffu, erL[hsel], o);
                elH[hsel] += __shfl_xor_sync(0xffffffffu, elH[hsel], o);
                erH[hsel] += __shfl_xor_sync(0xffffffffu, erH[hsel], o);
            }
        }
        if (t == 0) {
#pragma unroll
            for (int hsel = 0; hsel < 2; hsel++) {
                int head = head0 + hsel;
                if (v0) { g_el1[r0 * H1 + head] = elL[hsel]; g_er1[r0 * H1 + head] = erL[hsel]; }
                if (v1) { g_el1[r1 * H1 + head] = elH[hsel]; g_er1[r1 * H1 + head] = erH[hsel]; }
            }
        }
    }
}

// ---------------- GEMM2: fp16 mma + ldmatrix; 256 threads, 256-row blocks ----------------
__global__ __launch_bounds__(256) void hgemm2_kernel(
    int M, const float* __restrict__ al, const float* __restrict__ ar)
{
    extern __shared__ __half hsm[];
    __half* AsmD = hsm;                        // 2 * 256*40 halves
    __half* BsmD = hsm + 2 * 256 * 40;         // 2 * 64*40 halves

    const int tid = threadIdx.x;
    const int lane = tid & 31;
    const int warp = tid >> 5;
    const int g = lane >> 2;
    const int t = lane & 3;
    const int warpRow = warp * 32;
    const int blockRow = blockIdx.x * 256;

    const int arow = tid;                      // full 32-half chunk per thread (64B)
    const int agr = blockRow + arow;
    const int asz = (agr < M) ? 16 : 0;
    const __half* aSrc = g_h1h + (size_t)agr * KDIM;
    const int bcol = tid >> 2;                 // 0..63
    const int bseg = (tid & 3) * 8;            // halves
    const __half* bSrc = g_W2t + (size_t)bcol * KDIM + bseg;
    const uint32_t aD0 = smem_u32(AsmD + arow * 40);
    const uint32_t aD1 = aD0 + 20480;
    const uint32_t bD0 = smem_u32(BsmD + bcol * 40 + bseg);
    const uint32_t bD1 = bD0 + 5120;

    const uint32_t aL0 = smem_u32(AsmD) + (warpRow + (lane & 15)) * 80 + (lane >> 4) * 16;
    const uint32_t bL0 = smem_u32(BsmD) + ((lane & 7) + ((lane >> 4) << 3)) * 80 + (((lane >> 3) & 1) * 16);

    float acc[2][8][4];
#pragma unroll
    for (int mi = 0; mi < 2; mi++)
#pragma unroll
        for (int ni = 0; ni < 8; ni++)
#pragma unroll
            for (int k = 0; k < 4; k++) acc[mi][ni][k] = 0.f;

#pragma unroll
    for (int j = 0; j < 4; j++) CPA16(aD0 + j * 16, aSrc + j * 8, asz);
    CPA16(bD0, bSrc, 16);
    CP_COMMIT();

    for (int c = 0; c < 8; c++) {
        const int buf = c & 1;
        if (c < 7) {
            const __half* as = aSrc + (c + 1) * 32;
            const __half* bs = bSrc + (c + 1) * 32;
            uint32_t ad = buf ? aD0 : aD1;
            uint32_t bd = buf ? bD0 : bD1;
#pragma unroll
            for (int j = 0; j < 4; j++) CPA16(ad + j * 16, as + j * 8, asz);
            CPA16(bd, bs, 16);
        }
        CP_COMMIT();
        CP_WAIT1();
        __syncthreads();

        const uint32_t aB = aL0 + buf * 20480;
        const uint32_t bB = bL0 + buf * 5120;
#pragma unroll
        for (int s = 0; s < 2; s++) {
            uint32_t afr[2][4], bfr[8][2];
#pragma unroll
            for (int mi = 0; mi < 2; mi++)
                LDSM_X4(afr[mi][0], afr[mi][1], afr[mi][2], afr[mi][3],
                        aB + mi * (16 * 80) + s * 32);
#pragma unroll
            for (int p = 0; p < 4; p++)
                LDSM_X4(bfr[2 * p][0], bfr[2 * p][1], bfr[2 * p + 1][0], bfr[2 * p + 1][1],
                        bB + p * (16 * 80) + s * 32);
#pragma unroll
            for (int mi = 0; mi < 2; mi++)
#pragma unroll
                for (int ni = 0; ni < 8; ni++)
                    mma_f16(acc[mi][ni], afr[mi], bfr[ni]);
        }
        __syncthreads();
    }

#pragma unroll
    for (int mi = 0; mi < 2; mi++) {
        const int r0 = blockRow + warpRow + mi * 16 + g;
        const int r1 = r0 + 8;
        const bool v0 = r0 < M, v1 = r1 < M;
        float elA = 0.f, erA = 0.f, elB = 0.f, erB = 0.f;
#pragma unroll
        for (int ni = 0; ni < 8; ni++) {
            const int col = ni * 8 + 2 * t;
            float c0 = acc[mi][ni][0], c1 = acc[mi][ni][1];
            float c2 = acc[mi][ni][2], c3 = acc[mi][ni][3];
            float a0 = al[col], a1 = al[col + 1];
            float q0 = ar[col], q1 = ar[col + 1];
            elA += c0 * a0 + c1 * a1;  erA += c0 * q0 + c1 * q1;
            elB += c2 * a0 + c3 * a1;  erB += c2 * q0 + c3 * q1;
            if (v0) *(uint32_t*)&g_feat2h[(size_t)r0 * OUT_DIM + col] = h2_bits(__floats2half2_rn(c0, c1));
            if (v1) *(uint32_t*)&g_feat2h[(size_t)r1 * OUT_DIM + col] = h2_bits(__floats2half2_rn(c2, c3));
        }
#pragma unroll
        for (int o = 1; o <= 2; o <<= 1) {
            elA += __shfl_xor_sync(0xffffffffu, elA, o);
            erA += __shfl_xor_sync(0xffffffffu, erA, o);
            elB += __shfl_xor_sync(0xffffffffu, elB, o);
            erB += __shfl_xor_sync(0xffffffffu, erB, o);
        }
        if (t == 0) {
            if (v0) { g_el2[r0] = elA; g_er2[r0] = erA; }
            if (v1) { g_el2[r1] = elB; g_er2[r1] = erB; }
        }
    }
}

// ---------------- CSR build ----------------
__global__ void zero_cnt_kernel() {
    int i = blockIdx.x * blockDim.x + threadIdx.x;
    if (i < NNODES) g_cnt[i] = 0;
}

__global__ void hist_kernel(const int* __restrict__ dst) {
    int e = blockIdx.x * blockDim.x + threadIdx.x;
    if (e < NEDGES) atomicAdd(&g_cnt[dst[e]], 1);
}

__global__ void scan_kernel() {
    __shared__ int warpsum[32];
    int tid = threadIdx.x, lane = tid & 31, wid = tid >> 5;
    int carry = 0;
    for (int base = 0; base < NNODES; base += 4096) {
        int idx = base + tid * 4;
        int v0 = 0, v1 = 0, v2 = 0, v3 = 0;
        if (idx + 3 < NNODES) {
            int4 t = *(const int4*)&g_cnt[idx];
            v0 = t.x; v1 = t.y; v2 = t.z; v3 = t.w;
        } else {
            if (idx + 0 < NNODES) v0 = g_cnt[idx + 0];
            if (idx + 1 < NNODES) v1 = g_cnt[idx + 1];
            if (idx + 2 < NNODES) v2 = g_cnt[idx + 2];
            if (idx + 3 < NNODES) v3 = g_cnt[idx + 3];
        }
        int tsum = v0 + v1 + v2 + v3;
        int x = tsum;
#pragma unroll
        for (int o = 1; o < 32; o <<= 1) {
            int t = __shfl_up_sync(0xffffffffu, x, o);
            if (lane >= o) x += t;
        }
        if (lane == 31) warpsum[wid] = x;
        __syncthreads();
        if (wid == 0) {
            int w = warpsum[lane];
#pragma unroll
            for (int o = 1; o < 32; o <<= 1) {
                int t = __shfl_up_sync(0xffffffffu, w, o);
                if (lane >= o) w += t;
            }
            warpsum[lane] = w;
        }
        __syncthreads();
        int wexcl = (wid == 0) ? 0 : warpsum[wid - 1];
        int total = warpsum[31];
        int p = carry + wexcl + x - tsum;
        if (idx + 0 < NNODES) { g_off[idx + 0] = p;                g_cur[idx + 0] = p; }
        if (idx + 1 < NNODES) { g_off[idx + 1] = p + v0;           g_cur[idx + 1] = p + v0; }
        if (idx + 2 < NNODES) { g_off[idx + 2] = p + v0 + v1;      g_cur[idx + 2] = p + v0 + v1; }
        if (idx + 3 < NNODES) { g_off[idx + 3] = p + v0 + v1 + v2; g_cur[idx + 3] = p + v0 + v1 + v2; }
        carry += total;
        __syncthreads();
    }
    if (tid == 0) g_off[NNODES] = carry;
}

__global__ void scatter_kernel(const int* __restrict__ src, const int* __restrict__ dst) {
    int e = blockIdx.x * blockDim.x + threadIdx.x;
    if (e < NEDGES) {
        int p = atomicAdd(&g_cur[dst[e]], 1);
        g_csr_src[p] = src[e];
    }
}

// ---------------- layer 1 aggregation (4x unrolled) ----------------
__global__ void agg1_kernel(const float* __restrict__ b1) {
    int n = (blockIdx.x * blockDim.x + threadIdx.x) >> 5;
    if (n >= NNODES) return;
    int lane = threadIdx.x & 31;
    int hh = lane >> 2;
    int db = (lane & 3) * 8;

    float ern = g_er1[n * H1 + hh];
    float wsum = 0.f;
    float a[8];
#pragma unroll
    for (int k = 0; k < 8; k++) a[k] = 0.f;

    int beg = g_off[n], end = g_off[n + 1];
    int e = beg;
    for (; e + 4 <= end; e += 4) {
        int s0 = g_csr_src[e], s1 = g_csr_src[e + 1];
        int s2 = g_csr_src[e + 2], s3 = g_csr_src[e + 3];
        float x0 = g_el1[s0 * H1 + hh] + ern;
        float x1 = g_el1[s1 * H1 + hh] + ern;
        float x2 = g_el1[s2 * H1 + hh] + ern;
        float x3 = g_el1[s3 * H1 + hh] + ern;
        uint4 hv0 = *(const uint4*)(g_feat1h + (size_t)s0 * HD1 + hh * HID + db);
        uint4 hv1 = *(const uint4*)(g_feat1h + (size_t)s1 * HD1 + hh * HID + db);
        uint4 hv2 = *(const uint4*)(g_feat1h + (size_t)s2 * HD1 + hh * HID + db);
        uint4 hv3 = *(const uint4*)(g_feat1h + (size_t)s3 * HD1 + hh * HID + db);
        x0 = fmaxf(x0, 0.2f * x0); x1 = fmaxf(x1, 0.2f * x1);
        x2 = fmaxf(x2, 0.2f * x2); x3 = fmaxf(x3, 0.2f * x3);
        float w0 = __expf(x0), w1 = __expf(x1), w2 = __expf(x2), w3 = __expf(x3);
        wsum += (w0 + w1) + (w2 + w3);
        const __half2* hp0 = (const __half2*)&hv0;
        const __half2* hp1 = (const __half2*)&hv1;
        const __half2* hp2 = (const __half2*)&hv2;
        const __half2* hp3 = (const __half2*)&hv3;
#pragma unroll
        for (int j = 0; j < 4; j++) {
            float2 f0 = __half22float2(hp0[j]);
            float2 f1 = __half22float2(hp1[j]);
            float2 f2 = __half22float2(hp2[j]);
            float2 f3 = __half22float2(hp3[j]);
            a[2 * j + 0] += (w0 * f0.x + w1 * f1.x) + (w2 * f2.x + w3 * f3.x);
            a[2 * j + 1] += (w0 * f0.y + w1 * f1.y) + (w2 * f2.y + w3 * f3.y);
        }
    }
    for (; e < end; e++) {
        int s = g_csr_src[e];
        float x = g_el1[s * H1 + hh] + ern;
        x = fmaxf(x, 0.2f * x);
        float w = __expf(x);
        wsum += w;
        uint4 hv = *(const uint4*)(g_feat1h + (size_t)s * HD1 + hh * HID + db);
        const __half2* hp = (const __half2*)&hv;
#pragma unroll
        for (int j = 0; j < 4; j++) {
            float2 f = __half22float2(hp[j]);
            a[2 * j + 0] += w * f.x;
            a[2 * j + 1] += w * f.y;
        }
    }

    float inv = 1.f / wsum;
    const float* bp = b1 + hh * HID + db;
#pragma unroll
    for (int k = 0; k < 8; k++) {
        float v = a[k] * inv + bp[k];
        a[k] = v > 0.f ? v : (__expf(v) - 1.f);   // ELU
    }
    uint4 w = make_uint4(h2_bits(__floats2half2_rn(a[0], a[1])),
                         h2_bits(__floats2half2_rn(a[2], a[3])),
                         h2_bits(__floats2half2_rn(a[4], a[5])),
                         h2_bits(__floats2half2_rn(a[6], a[7])));
    *(uint4*)&g_h1h[(size_t)n * HD1 + hh * HID + db] = w;
}

// ---------------- layer 2 aggregation (4x unrolled) ----------------
__global__ void agg2_kernel(const float* __restrict__ b2, float* __restrict__ out) {
    int n = (blockIdx.x * blockDim.x + threadIdx.x) >> 5;
    if (n >= NNODES) return;
    int lane = threadIdx.x & 31;

    float ern = g_er2[n];
    float wsum = 0.f;
    float a0 = 0.f, a1 = 0.f;

    int beg = g_off[n], end = g_off[n + 1];
    int e = beg;
    for (; e + 4 <= end; e += 4) {
        int s0 = g_csr_src[e], s1 = g_csr_src[e + 1];
        int s2 = g_csr_src[e + 2], s3 = g_csr_src[e + 3];
        float x0 = g_el2[s0] + ern;
        float x1 = g_el2[s1] + ern;
        float x2 = g_el2[s2] + ern;
        float x3 = g_el2[s3] + ern;
        __half2 hv0 = *(const __half2*)(g_feat2h + (size_t)s0 * OUT_DIM + lane * 2);
        __half2 hv1 = *(const __half2*)(g_feat2h + (size_t)s1 * OUT_DIM + lane * 2);
        __half2 hv2 = *(const __half2*)(g_feat2h + (size_t)s2 * OUT_DIM + lane * 2);
        __half2 hv3 = *(const __half2*)(g_feat2h + (size_t)s3 * OUT_DIM + lane * 2);
        x0 = fmaxf(x0, 0.2f * x0); x1 = fmaxf(x1, 0.2f * x1);
        x2 = fmaxf(x2, 0.2f * x2); x3 = fmaxf(x3, 0.2f * x3);
        float w0 = __expf(x0), w1 = __expf(x1), w2 = __expf(x2), w3 = __expf(x3);
        wsum += (w0 + w1) + (w2 + w3);
        float2 f0 = __half22float2(hv0);
        float2 f1 = __half22float2(hv1);
        float2 f2 = __half22float2(hv2);
        float2 f3 = __half22float2(hv3);
        a0 += (w0 * f0.x + w1 * f1.x) + (w2 * f2.x + w3 * f3.x);
        a1 += (w0 * f0.y + w1 * f1.y) + (w2 * f2.y + w3 * f3.y);
    }
    for (; e < end; e++) {
        int s = g_csr_src[e];
        float x = g_el2[s] + ern;
        x = fmaxf(x, 0.2f * x);
        float w = __expf(x);
        wsum += w;
        float2 f = __half22float2(*(const __half2*)(g_feat2h + (size_t)s * OUT_DIM + lane * 2));
        a0 += w * f.x;
        a1 += w * f.y;
    }

    float inv = 1.f / wsum;
    out[(size_t)n * OUT_DIM + lane * 2 + 0] = a0 * inv + b2[lane * 2 + 0];
    out[(size_t)n * OUT_DIM + lane * 2 + 1] = a1 * inv + b2[lane * 2 + 1];
}

// ---------------- launch ----------------
extern "C" void kernel_launch(void* const* d_in, const int* in_sizes, int n_in,
                              void* d_out, int out_size) {
    const float* h   = (const float*)d_in[0];
    const float* W1  = (const float*)d_in[1];
    const float* al1 = (const float*)d_in[2];
    const float* ar1 = (const float*)d_in[3];
    const float* b1  = (const float*)d_in[4];
    const float* W2  = (const float*)d_in[5];
    const float* al2 = (const float*)d_in[6];
    const float* ar2 = (const float*)d_in[7];
    const float* b2  = (const float*)d_in[8];
    const int*   src = (const int*)d_in[9];
    const int*   dst = (const int*)d_in[10];
    float* out = (float*)d_out;

    const int SMEM_G2 = (2 * 256 * 40 + 2 * 64 * 40) * 2;   // 51200 B
    static bool attr_done = false;
    if (!attr_done) {
        cudaFuncSetAttribute((const void*)hgemm2_kernel, cudaFuncAttributeMaxDynamicSharedMemorySize, SMEM_G2);
        attr_done = true;
    }

    static cudaStream_t s_csr = nullptr;
    static cudaEvent_t ev_fork = nullptr, ev_join = nullptr;
    if (s_csr == nullptr) {
        cudaStreamCreateWithFlags(&s_csr, cudaStreamNonBlocking);
        cudaEventCreateWithFlags(&ev_fork, cudaEventDisableTiming);
        cudaEventCreateWithFlags(&ev_join, cudaEventDisableTiming);
    }

    const int nwarpblocks = (NNODES * 32 + 255) / 256;
    const int eblocks = (NEDGES + 255) / 256;
    const int gblocks = (NNODES + 127) / 128;        // 391
    const int g2blocks = (NNODES + 255) / 256;       // 196

    cudaEventRecord(ev_fork, 0);
    cudaStreamWaitEvent(s_csr, ev_fork, 0);
    zero_cnt_kernel<<<(NNODES + 255) / 256, 256, 0, s_csr>>>();          // 1
    hist_kernel<<<eblocks, 256, 0, s_csr>>>(dst);                        // 2
    prepw_kernel<<<320, 256>>>(W1, W2);                                  // 3 (main)
    hgemm1_kernel<<<dim3(2, gblocks), 256>>>(h, NNODES, al1, ar1);       // 4 (main, ncu window)
    scan_kernel<<<1, 1024, 0, s_csr>>>();                                // 5
    scatter_kernel<<<eblocks, 256, 0, s_csr>>>(src, dst);                // 6
    cudaEventRecord(ev_join, s_csr);

    cudaStreamWaitEvent(0, ev_join, 0);
    agg1_kernel<<<nwarpblocks, 256>>>(b1);                               // 7
    hgemm2_kernel<<<g2blocks, 256, SMEM_G2>>>(NNODES, al2, ar2);         // 8
    agg2_kernel<<<nwarpblocks, 256>>>(b2, out);                          // 9
}

// round 17
// speedup vs baseline: 1.0365x; 1.0365x over previous
#include <cuda_runtime.h>
#include <cuda_fp16.h>
#include <cstdint>

#define NNODES 50000
#define NEDGES 850000
#define IN_DIM 256
#define HID 32
#define H1 8
#define OUT_DIM 64
#define HD1 (H1*HID)   // 256
#define KDIM 256

// ---------------- scratch ----------------
__device__ __align__(16) __half g_W1t[HD1 * KDIM];
__device__ __align__(16) __half g_W2t[OUT_DIM * KDIM];
__device__ __align__(16) __half g_feat1h[NNODES * HD1];
__device__ __align__(16) __half g_h1h[NNODES * HD1];
__device__ __align__(16) __half g_feat2h[NNODES * OUT_DIM];
__device__ __align__(16) float  g_el1[NNODES * H1];
__device__ __align__(16) float  g_er1[NNODES * H1];
__device__ __align__(16) float  g_el2[NNODES];
__device__ __align__(16) float  g_er2[NNODES];
__device__ __align__(16) int    g_cnt[NNODES];
__device__ __align__(16) int    g_off[NNODES + 1];
__device__ __align__(16) int    g_cur[NNODES];
__device__ __align__(16) int    g_csr_src[NEDGES];

#define CPA16(dst, src, sz) \
    asm volatile("cp.async.cg.shared.global [%0], [%1], 16, %2;" :: "r"(dst), "l"(src), "r"(sz) : "memory")
#define CP_COMMIT() asm volatile("cp.async.commit_group;" ::: "memory")
#define CP_WAIT1()  asm volatile("cp.async.wait_group 1;" ::: "memory")

#define LDSM_X4(r0, r1, r2, r3, addr) \
    asm volatile("ldmatrix.sync.aligned.m8n8.x4.shared.b16 {%0,%1,%2,%3}, [%4];" \
        : "=r"(r0), "=r"(r1), "=r"(r2), "=r"(r3) : "r"(addr))

__device__ __forceinline__ uint32_t smem_u32(const void* p) {
    uint32_t a;
    asm("{ .reg .u64 t; cvta.to.shared.u64 t, %1; cvt.u32.u64 %0, t; }" : "=r"(a) : "l"(p));
    return a;
}
__device__ __forceinline__ uint32_t h2_bits(__half2 h) {
    uint32_t u;
    memcpy(&u, &h, 4);
    return u;
}

__device__ __forceinline__ void mma_f16(float c[4], const uint32_t a[4], const uint32_t b[2]) {
    asm("mma.sync.aligned.m16n8k16.row.col.f32.f16.f16.f32 "
        "{%0,%1,%2,%3}, {%4,%5,%6,%7}, {%8,%9}, {%0,%1,%2,%3};"
        : "+f"(c[0]), "+f"(c[1]), "+f"(c[2]), "+f"(c[3])
        : "r"(a[0]), "r"(a[1]), "r"(a[2]), "r"(a[3]), "r"(b[0]), "r"(b[1]));
}

// ---------------- prep: weight transposes only ----------------
__global__ void prepw_kernel(const float* __restrict__ W1, const float* __restrict__ W2) {
    int b = blockIdx.x;
    if (b < 256) {
        int i = b * 256 + threadIdx.x;
        int n = i >> 8, k = i & 255;
        g_W1t[i] = __float2half(W1[k * HD1 + n]);
    } else {
        int i = (b - 256) * 256 + threadIdx.x;
        int n = i >> 8, k = i & 255;
        g_W2t[i] = __float2half(W2[k * OUT_DIM + n]);
    }
}

// ---------------- GEMM1: fp16 mma + ldmatrix; A converted fp32->fp16 in-kernel ----------------
// Block 128 rows x 128 cols; 8 warps (4m x 2n); warp tile 32x64. Smem stride 40 halves (80B).
__global__ __launch_bounds__(256) void hgemm1_kernel(
    const float* __restrict__ A, int M, const float* __restrict__ al, const float* __restrict__ ar)
{
    __shared__ __align__(16) __half Asm[2][128 * 40];
    __shared__ __align__(16) __half Bsm[2][128 * 40];

    const int tid = threadIdx.x;
    const int lane = tid & 31;
    const int warp = tid >> 5;
    const int g = lane >> 2;
    const int t = lane & 3;
    const int warpRow = (warp & 3) * 32;
    const int warpCol = (warp >> 2) * 64;
    const int blockRow = blockIdx.y * 128;
    const int colbase = blockIdx.x * 128;

    const int arow = tid >> 1;
    const int kh = (tid & 1) * 16;
    const int agr = blockRow + arow;
    const bool aval = agr < M;
    const float* aSrc = A + (size_t)agr * KDIM + kh;
    __half* aDst0 = &Asm[0][arow * 40 + kh];

    const int bcol = tid >> 1;
    const int bseg = (tid & 1) * 16;
    const __half* bSrc = g_W1t + (size_t)(colbase + bcol) * KDIM + bseg;
    const uint32_t bD0 = smem_u32(&Bsm[0][bcol * 40 + bseg]);
    const uint32_t bD1 = smem_u32(&Bsm[1][bcol * 40 + bseg]);

    const uint32_t aL0 = smem_u32(&Asm[0][0]) + (warpRow + (lane & 15)) * 80 + (lane >> 4) * 16;
    const uint32_t bL0 = smem_u32(&Bsm[0][0]) + (warpCol + (lane & 7) + ((lane >> 4) << 3)) * 80 + (((lane >> 3) & 1) * 16);

    float acc[2][8][4];
#pragma unroll
    for (int mi = 0; mi < 2; mi++)
#pragma unroll
        for (int ni = 0; ni < 8; ni++)
#pragma unroll
            for (int k = 0; k < 4; k++) acc[mi][ni][k] = 0.f;

    float4 av[4];
    auto ldgA = [&](int c) {
#pragma unroll
        for (int q = 0; q < 4; q++)
            av[q] = aval ? *(const float4*)(aSrc + c * 32 + q * 4)
                         : make_float4(0.f, 0.f, 0.f, 0.f);
    };
    auto stsA = [&](int buf) {
        __half* d = aDst0 + buf * (128 * 40);
        uint4 w0, w1;
        w0.x = h2_bits(__floats2half2_rn(av[0].x, av[0].y));
        w0.y = h2_bits(__floats2half2_rn(av[0].z, av[0].w));
        w0.z = h2_bits(__floats2half2_rn(av[1].x, av[1].y));
        w0.w = h2_bits(__floats2half2_rn(av[1].z, av[1].w));
        w1.x = h2_bits(__floats2half2_rn(av[2].x, av[2].y));
        w1.y = h2_bits(__floats2half2_rn(av[2].z, av[2].w));
        w1.z = h2_bits(__floats2half2_rn(av[3].x, av[3].y));
        w1.w = h2_bits(__floats2half2_rn(av[3].z, av[3].w));
        *(uint4*)d = w0;
        *(uint4*)(d + 8) = w1;
    };
    auto cpB = [&](int c, int buf) {
        const __half* s = bSrc + c * 32;
        uint32_t d = buf ? bD1 : bD0;
        CPA16(d, s, 16);
        CPA16(d + 16, s + 8, 16);
    };

    ldgA(0); stsA(0);
    cpB(0, 0); CP_COMMIT();
    ldgA(1);

    for (int c = 0; c < 8; c++) {
        const int buf = c & 1;
        if (c < 7) cpB(c + 1, buf ^ 1);
        CP_COMMIT();
        CP_WAIT1();
        __syncthreads();

        const uint32_t aB = aL0 + buf * 10240;
        const uint32_t bB = bL0 + buf * 10240;
#pragma unroll
        for (int s = 0; s < 2; s++) {
            uint32_t afr[2][4], bfr[8][2];
#pragma unroll
            for (int mi = 0; mi < 2; mi++)
                LDSM_X4(afr[mi][0], afr[mi][1], afr[mi][2], afr[mi][3],
                        aB + mi * (16 * 80) + s * 32);
#pragma unroll
            for (int p = 0; p < 4; p++)
                LDSM_X4(bfr[2 * p][0], bfr[2 * p][1], bfr[2 * p + 1][0], bfr[2 * p + 1][1],
                        bB + p * (16 * 80) + s * 32);
#pragma unroll
            for (int mi = 0; mi < 2; mi++)
#pragma unroll
                for (int ni = 0; ni < 8; ni++)
                    mma_f16(acc[mi][ni], afr[mi], bfr[ni]);
        }
        if (c < 7) {
            stsA(buf ^ 1);
            if (c < 6) ldgA(c + 2);
        }
        __syncthreads();
    }

    const int head0 = (colbase + warpCol) >> 5;
#pragma unroll
    for (int mi = 0; mi < 2; mi++) {
        const int r0 = blockRow + warpRow + mi * 16 + g;
        const int r1 = r0 + 8;
        const bool v0 = r0 < M, v1 = r1 < M;
        float elL[2] = {0.f, 0.f}, erL[2] = {0.f, 0.f};
        float elH[2] = {0.f, 0.f}, erH[2] = {0.f, 0.f};
#pragma unroll
        for (int ni = 0; ni < 8; ni++) {
            const int hsel = ni >> 2;
            const int col = colbase + warpCol + ni * 8 + 2 * t;
            float c0 = acc[mi][ni][0], c1 = acc[mi][ni][1];
            float c2 = acc[mi][ni][2], c3 = acc[mi][ni][3];
            float a0 = al[col], a1 = al[col + 1];
            float q0 = ar[col], q1 = ar[col + 1];
            elL[hsel] += c0 * a0 + c1 * a1;  erL[hsel] += c0 * q0 + c1 * q1;
            elH[hsel] += c2 * a0 + c3 * a1;  erH[hsel] += c2 * q0 + c3 * q1;
            if (v0) *(uint32_t*)&g_feat1h[(size_t)r0 * HD1 + col] = h2_bits(__floats2half2_rn(c0, c1));
            if (v1) *(uint32_t*)&g_feat1h[(size_t)r1 * HD1 + col] = h2_bits(__floats2half2_rn(c2, c3));
        }
#pragma unroll
        for (int hsel = 0; hsel < 2; hsel++) {
#pragma unroll
            for (int o = 1; o <= 2; o <<= 1) {
                elL[hsel] += __shfl_xor_sync(0xffffffffu, elL[hsel], o);
                erL[hsel] += __shfl_xor_sync(0xffffffffu, erL[hsel], o);
                elH[hsel] += __shfl_xor_sync(0xffffffffu, elH[hsel], o);
                erH[hsel] += __shfl_xor_sync(0xffffffffu, erH[hsel], o);
            }
        }
        if (t == 0) {
#pragma unroll
            for (int hsel = 0; hsel < 2; hsel++) {
                int head = head0 + hsel;
                if (v0) { g_el1[r0 * H1 + head] = elL[hsel]; g_er1[r0 * H1 + head] = erL[hsel]; }
                if (v1) { g_el1[r1 * H1 + head] = elH[hsel]; g_er1[r1 * H1 + head] = erH[hsel]; }
            }
        }
    }
}

// ---------------- GEMM2: fp16 mma + ldmatrix, 4 warps, 128-row blocks (R13 champion version) ----------------
__global__ __launch_bounds__(128) void hgemm2_kernel(
    int M, const float* __restrict__ al, const float* __restrict__ ar)
{
    __shared__ __align__(16) __half Asm[2][128 * 40];
    __shared__ __align__(16) __half Bsm[2][64 * 40];

    const int tid = threadIdx.x;
    const int lane = tid & 31;
    const int warp = tid >> 5;
    const int g = lane >> 2;
    const int t = lane & 3;
    const int warpRow = warp * 32;
    const int blockRow = blockIdx.x * 128;

    const int arow = tid;
    const int agr = blockRow + arow;
    const int asz = (agr < M) ? 16 : 0;
    const __half* aSrc = g_h1h + (size_t)agr * KDIM;
    const int bcol = tid >> 1;
    const int bseg = (tid & 1) * 16;
    const __half* bSrc = g_W2t + (size_t)bcol * KDIM + bseg;
    const uint32_t aD0 = smem_u32(&Asm[0][arow * 40]);
    const uint32_t aD1 = smem_u32(&Asm[1][arow * 40]);
    const uint32_t bD0 = smem_u32(&Bsm[0][bcol * 40 + bseg]);
    const uint32_t bD1 = smem_u32(&Bsm[1][bcol * 40 + bseg]);

    const uint32_t aL0 = smem_u32(&Asm[0][0]) + (warpRow + (lane & 15)) * 80 + (lane >> 4) * 16;
    const uint32_t bL0 = smem_u32(&Bsm[0][0]) + ((lane & 7) + ((lane >> 4) << 3)) * 80 + (((lane >> 3) & 1) * 16);

    float acc[2][8][4];
#pragma unroll
    for (int mi = 0; mi < 2; mi++)
#pragma unroll
        for (int ni = 0; ni < 8; ni++)
#pragma unroll
            for (int k = 0; k < 4; k++) acc[mi][ni][k] = 0.f;

#pragma unroll
    for (int j = 0; j < 4; j++) CPA16(aD0 + j * 16, aSrc + j * 8, asz);
    CPA16(bD0, bSrc, 16);
    CPA16(bD0 + 16, bSrc + 8, 16);
    CP_COMMIT();

    for (int c = 0; c < 8; c++) {
        const int buf = c & 1;
        if (c < 7) {
            const __half* as = aSrc + (c + 1) * 32;
            const __half* bs = bSrc + (c + 1) * 32;
            uint32_t ad = buf ? aD0 : aD1;
            uint32_t bd = buf ? bD0 : bD1;
#pragma unroll
            for (int j = 0; j < 4; j++) CPA16(ad + j * 16, as + j * 8, asz);
            CPA16(bd, bs, 16);
            CPA16(bd + 16, bs + 8, 16);
        }
        CP_COMMIT();
        CP_WAIT1();
        __syncthreads();

        const uint32_t aB = aL0 + buf * 10240;
        const uint32_t bB = bL0 + buf * 5120;
#pragma unroll
        for (int s = 0; s < 2; s++) {
            uint32_t afr[2][4], bfr[8][2];
#pragma unroll
            for (int mi = 0; mi < 2; mi++)
                LDSM_X4(afr[mi][0], afr[mi][1], afr[mi][2], afr[mi][3],
                        aB + mi * (16 * 80) + s * 32);
#pragma unroll
            for (int p = 0; p < 4; p++)
                LDSM_X4(bfr[2 * p][0], bfr[2 * p][1], bfr[2 * p + 1][0], bfr[2 * p + 1][1],
                        bB + p * (16 * 80) + s * 32);
#pragma unroll
            for (int mi = 0; mi < 2; mi++)
#pragma unroll
                for (int ni = 0; ni < 8; ni++)
                    mma_f16(acc[mi][ni], afr[mi], bfr[ni]);
        }
        __syncthreads();
    }

#pragma unroll
    for (int mi = 0; mi < 2; mi++) {
        const int r0 = blockRow + warpRow + mi * 16 + g;
        const int r1 = r0 + 8;
        const bool v0 = r0 < M, v1 = r1 < M;
        float elA = 0.f, erA = 0.f, elB = 0.f, erB = 0.f;
#pragma unroll
        for (int ni = 0; ni < 8; ni++) {
            const int col = ni * 8 + 2 * t;
            float c0 = acc[mi][ni][0], c1 = acc[mi][ni][1];
            float c2 = acc[mi][ni][2], c3 = acc[mi][ni][3];
            float a0 = al[col], a1 = al[col + 1];
            float q0 = ar[col], q1 = ar[col + 1];
            elA += c0 * a0 + c1 * a1;  erA += c0 * q0 + c1 * q1;
            elB += c2 * a0 + c3 * a1;  erB += c2 * q0 + c3 * q1;
            if (v0) *(uint32_t*)&g_feat2h[(size_t)r0 * OUT_DIM + col] = h2_bits(__floats2half2_rn(c0, c1));
            if (v1) *(uint32_t*)&g_feat2h[(size_t)r1 * OUT_DIM + col] = h2_bits(__floats2half2_rn(c2, c3));
        }
#pragma unroll
        for (int o = 1; o <= 2; o <<= 1) {
            elA += __shfl_xor_sync(0xffffffffu, elA, o);
            erA += __shfl_xor_sync(0xffffffffu, erA, o);
            elB += __shfl_xor_sync(0xffffffffu, elB, o);
            erB += __shfl_xor_sync(0xffffffffu, erB, o);
        }
        if (t == 0) {
            if (v0) { g_el2[r0] = elA; g_er2[r0] = erA; }
            if (v1) { g_el2[r1] = elB; g_er2[r1] = erB; }
        }
    }
}

// ---------------- CSR build ----------------
__global__ void zero_cnt_kernel() {
    int i = blockIdx.x * blockDim.x + threadIdx.x;
    if (i < NNODES) g_cnt[i] = 0;
}

__global__ void hist_kernel(const int* __restrict__ dst) {
    int e = blockIdx.x * blockDim.x + threadIdx.x;
    if (e < NEDGES) atomicAdd(&g_cnt[dst[e]], 1);
}

__global__ void scan_kernel() {
    __shared__ int warpsum[32];
    int tid = threadIdx.x, lane = tid & 31, wid = tid >> 5;
    int carry = 0;
    for (int base = 0; base < NNODES; base += 4096) {
        int idx = base + tid * 4;
        int v0 = 0, v1 = 0, v2 = 0, v3 = 0;
        if (idx + 3 < NNODES) {
            int4 t = *(const int4*)&g_cnt[idx];
            v0 = t.x; v1 = t.y; v2 = t.z; v3 = t.w;
        } else {
            if (idx + 0 < NNODES) v0 = g_cnt[idx + 0];
            if (idx + 1 < NNODES) v1 = g_cnt[idx + 1];
            if (idx + 2 < NNODES) v2 = g_cnt[idx + 2];
            if (idx + 3 < NNODES) v3 = g_cnt[idx + 3];
        }
        int tsum = v0 + v1 + v2 + v3;
        int x = tsum;
#pragma unroll
        for (int o = 1; o < 32; o <<= 1) {
            int t = __shfl_up_sync(0xffffffffu, x, o);
            if (lane >= o) x += t;
        }
        if (lane == 31) warpsum[wid] = x;
        __syncthreads();
        if (wid == 0) {
            int w = warpsum[lane];
#pragma unroll
            for (int o = 1; o < 32; o <<= 1) {
                int t = __shfl_up_sync(0xffffffffu, w, o);
                if (lane >= o) w += t;
            }
            warpsum[lane] = w;
        }
        __syncthreads();
        int wexcl = (wid == 0) ? 0 : warpsum[wid - 1];
        int total = warpsum[31];
        int p = carry + wexcl + x - tsum;
        if (idx + 0 < NNODES) { g_off[idx + 0] = p;                g_cur[idx + 0] = p; }
        if (idx + 1 < NNODES) { g_off[idx + 1] = p + v0;           g_cur[idx + 1] = p + v0; }
        if (idx + 2 < NNODES) { g_off[idx + 2] = p + v0 + v1;      g_cur[idx + 2] = p + v0 + v1; }
        if (idx + 3 < NNODES) { g_off[idx + 3] = p + v0 + v1 + v2; g_cur[idx + 3] = p + v0 + v1 + v2; }
        carry += total;
        __syncthreads();
    }
    if (tid == 0) g_off[NNODES] = carry;
}

__global__ void scatter_kernel(const int* __restrict__ src, const int* __restrict__ dst) {
    int e = blockIdx.x * blockDim.x + threadIdx.x;
    if (e < NEDGES) {
        int p = atomicAdd(&g_cur[dst[e]], 1);
        g_csr_src[p] = src[e];
    }
}

// ---------------- layer 1 aggregation (2x unrolled, fp16 feats, fp16 h1 out) ----------------
__global__ void agg1_kernel(const float* __restrict__ b1) {
    int n = (blockIdx.x * blockDim.x + threadIdx.x) >> 5;
    if (n >= NNODES) return;
    int lane = threadIdx.x & 31;
    int hh = lane >> 2;
    int db = (lane & 3) * 8;

    float ern = g_er1[n * H1 + hh];
    float wsum = 0.f;
    float a[8];
#pragma unroll
    for (int k = 0; k < 8; k++) a[k] = 0.f;

    int beg = g_off[n], end = g_off[n + 1];
    int e = beg;
    for (; e + 2 <= end; e += 2) {
        int s0 = g_csr_src[e], s1 = g_csr_src[e + 1];
        float x0 = g_el1[s0 * H1 + hh] + ern;
        float x1 = g_el1[s1 * H1 + hh] + ern;
        uint4 hv0 = *(const uint4*)(g_feat1h + (size_t)s0 * HD1 + hh * HID + db);
        uint4 hv1 = *(const uint4*)(g_feat1h + (size_t)s1 * HD1 + hh * HID + db);
        x0 = fmaxf(x0, 0.2f * x0);
        x1 = fmaxf(x1, 0.2f * x1);
        float w0 = __expf(x0), w1 = __expf(x1);
        wsum += w0 + w1;
        const __half2* hp0 = (const __half2*)&hv0;
        const __half2* hp1 = (const __half2*)&hv1;
#pragma unroll
        for (int j = 0; j < 4; j++) {
            float2 f0 = __half22float2(hp0[j]);
            float2 f1 = __half22float2(hp1[j]);
            a[2 * j + 0] += w0 * f0.x + w1 * f1.x;
            a[2 * j + 1] += w0 * f0.y + w1 * f1.y;
        }
    }
    if (e < end) {
        int s = g_csr_src[e];
        float x = g_el1[s * H1 + hh] + ern;
        x = fmaxf(x, 0.2f * x);
        float w = __expf(x);
        wsum += w;
        uint4 hv = *(const uint4*)(g_feat1h + (size_t)s * HD1 + hh * HID + db);
        const __half2* hp = (const __half2*)&hv;
#pragma unroll
        for (int j = 0; j < 4; j++) {
            float2 f = __half22float2(hp[j]);
            a[2 * j + 0] += w * f.x;
            a[2 * j + 1] += w * f.y;
        }
    }

    float inv = 1.f / wsum;
    const float* bp = b1 + hh * HID + db;
#pragma unroll
    for (int k = 0; k < 8; k++) {
        float v = a[k] * inv + bp[k];
        a[k] = v > 0.f ? v : (__expf(v) - 1.f);   // ELU
    }
    uint4 w = make_uint4(h2_bits(__floats2half2_rn(a[0], a[1])),
                         h2_bits(__floats2half2_rn(a[2], a[3])),
                         h2_bits(__floats2half2_rn(a[4], a[5])),
                         h2_bits(__floats2half2_rn(a[6], a[7])));
    *(uint4*)&g_h1h[(size_t)n * HD1 + hh * HID + db] = w;
}

// ---------------- layer 2 aggregation (fp16 feats, 2x unrolled) ----------------
__global__ void agg2_kernel(const float* __restrict__ b2, float* __restrict__ out) {
    int n = (blockIdx.x * blockDim.x + threadIdx.x) >> 5;
    if (n >= NNODES) return;
    int lane = threadIdx.x & 31;

    float ern = g_er2[n];
    float wsum = 0.f;
    float a0 = 0.f, a1 = 0.f;

    int beg = g_off[n], end = g_off[n + 1];
    int e = beg;
    for (; e + 2 <= end; e += 2) {
        int s0 = g_csr_src[e], s1 = g_csr_src[e + 1];
        float x0 = g_el2[s0] + ern;
        float x1 = g_el2[s1] + ern;
        __half2 hv0 = *(const __half2*)(g_feat2h + (size_t)s0 * OUT_DIM + lane * 2);
        __half2 hv1 = *(const __half2*)(g_feat2h + (size_t)s1 * OUT_DIM + lane * 2);
        x0 = fmaxf(x0, 0.2f * x0);
        x1 = fmaxf(x1, 0.2f * x1);
        float w0 = __expf(x0), w1 = __expf(x1);
        wsum += w0 + w1;
        float2 f0 = __half22float2(hv0);
        float2 f1 = __half22float2(hv1);
        a0 += w0 * f0.x + w1 * f1.x;
        a1 += w0 * f0.y + w1 * f1.y;
    }
    if (e < end) {
        int s = g_csr_src[e];
        float x = g_el2[s] + ern;
        x = fmaxf(x, 0.2f * x);
        float w = __expf(x);
        wsum += w;
        float2 f = __half22float2(*(const __half2*)(g_feat2h + (size_t)s * OUT_DIM + lane * 2));
        a0 += w * f.x;
        a1 += w * f.y;
    }

    float inv = 1.f / wsum;
    out[(size_t)n * OUT_DIM + lane * 2 + 0] = a0 * inv + b2[lane * 2 + 0];
    out[(size_t)n * OUT_DIM + lane * 2 + 1] = a1 * inv + b2[lane * 2 + 1];
}

// ---------------- launch ----------------
extern "C" void kernel_launch(void* const* d_in, const int* in_sizes, int n_in,
                              void* d_out, int out_size) {
    const float* h   = (const float*)d_in[0];
    const float* W1  = (const float*)d_in[1];
    const float* al1 = (const float*)d_in[2];
    const float* ar1 = (const float*)d_in[3];
    const float* b1  = (const float*)d_in[4];
    const float* W2  = (const float*)d_in[5];
    const float* al2 = (const float*)d_in[6];
    const float* ar2 = (const float*)d_in[7];
    const float* b2  = (const float*)d_in[8];
    const int*   src = (const int*)d_in[9];
    const int*   dst = (const int*)d_in[10];
    float* out = (float*)d_out;

    static cudaStream_t s_csr = nullptr;
    static cudaEvent_t ev_fork = nullptr, ev_join = nullptr;
    if (s_csr == nullptr) {
        cudaStreamCreateWithFlags(&s_csr, cudaStreamNonBlocking);
        cudaEventCreateWithFlags(&ev_fork, cudaEventDisableTiming);
        cudaEventCreateWithFlags(&ev_join, cudaEventDisableTiming);
    }

    const int nwarpblocks = (NNODES * 32 + 255) / 256;
    const int eblocks = (NEDGES + 255) / 256;
    const int gblocks = (NNODES + 127) / 128;        // 391

    cudaEventRecord(ev_fork, 0);
    cudaStreamWaitEvent(s_csr, ev_fork, 0);
    zero_cnt_kernel<<<(NNODES + 255) / 256, 256, 0, s_csr>>>();          // 1
    hist_kernel<<<eblocks, 256, 0, s_csr>>>(dst);                        // 2
    prepw_kernel<<<320, 256>>>(W1, W2);                                  // 3 (main)
    hgemm1_kernel<<<dim3(2, gblocks), 256>>>(h, NNODES, al1, ar1);       // 4 (main, ncu window)
    scan_kernel<<<1, 1024, 0, s_csr>>>();                                // 5
    scatter_kernel<<<eblocks, 256, 0, s_csr>>>(src, dst);                // 6
    cudaEventRecord(ev_join, s_csr);

    cudaStreamWaitEvent(0, ev_join, 0);
    agg1_kernel<<<nwarpblocks, 256>>>(b1);                               // 7
    hgemm2_kernel<<<gblocks, 128>>>(NNODES, al2, ar2);                   // 8
    agg2_kernel<<<nwarpblocks, 256>>>(b2, out);                          // 9
}